// round 7
// baseline (speedup 1.0000x reference)
#include <cuda_runtime.h>
#include <cstdint>

// LIF neuron scan — balanced persistent tiling: 148 CTAs (1/SM), each owning
// 6-7 units of (batch, 32 neurons), TMA-read pipeline, register compute,
// streamed scalar stores.
//
// Inputs : d_in[0] = input_current  f32 [B=32, T=1000, N=1024]
//          d_in[1] = v_init         f32 [B=32, N=1024]
// Output : d_out = [2, B, T, N] f32  (spikes block, then voltages block)
//
// Recurrence:
//   v = v + (i - v) / 10.0     (correctly-rounded div via Markstein FMA seq)
//   s = (v >= 1.0) ? 1 : 0
//   v = s ? 0 : v

#define LIF_B   32
#define LIF_T   1000
#define LIF_N   1024
#define TC      20                     // timesteps per chunk
#define NSTAGE  8                      // input pipeline depth
#define MAXU    7                      // max units (32-neuron blocks) per CTA
#define NTHREAD (MAXU * 32)            // 224 threads
#define NCHUNK  (LIF_T / TC)           // 50
#define UNIT_ROW_BYTES 128             // 32 floats
#define NCTA    148

struct LifSmem {
    float tile[NSTAGE][TC][NTHREAD];   // 8*20*224*4 = 143360 B
    unsigned long long mbar[NSTAGE];
};

static __device__ __forceinline__ unsigned smem_u32(const void* p) {
    return (unsigned)__cvta_generic_to_shared(p);
}

static __device__ __forceinline__ void mbar_init(unsigned mbar, unsigned count) {
    asm volatile("mbarrier.init.shared.b64 [%0], %1;" :: "r"(mbar), "r"(count) : "memory");
}

static __device__ __forceinline__ void mbar_expect_tx(unsigned mbar, unsigned bytes) {
    asm volatile("mbarrier.arrive.expect_tx.shared.b64 _, [%0], %1;"
                 :: "r"(mbar), "r"(bytes) : "memory");
}

static __device__ __forceinline__ void mbar_wait(unsigned mbar, unsigned parity) {
    asm volatile(
        "{\n\t"
        ".reg .pred P1;\n\t"
        "LAB_WAIT_%=:\n\t"
        "mbarrier.try_wait.parity.acquire.cta.shared::cta.b64 P1, [%0], %1, 0x989680;\n\t"
        "@P1 bra LAB_DONE_%=;\n\t"
        "bra LAB_WAIT_%=;\n\t"
        "LAB_DONE_%=:\n\t"
        "}"
        :: "r"(mbar), "r"(parity) : "memory");
}

static __device__ __forceinline__ void bulk_g2s(unsigned dst_smem, const void* gsrc,
                                                unsigned bytes, unsigned mbar) {
    asm volatile(
        "cp.async.bulk.shared::cta.global.mbarrier::complete_tx::bytes [%0], [%1], %2, [%3];"
        :: "r"(dst_smem), "l"(gsrc), "r"(bytes), "r"(mbar) : "memory");
}

static __device__ __forceinline__ float lif_step(float v, float i, float& s_out) {
    float x  = i - v;                  // (-(v - 0) + i)
    float q0 = x * 0.1f;               // Markstein: correctly-rounded x/10
    float e  = fmaf(-10.0f, q0, x);
    float q  = fmaf(e, 0.1f, q0);
    v = v + q;
    s_out = (v >= 1.0f) ? 1.0f : 0.0f;
    return (v >= 1.0f) ? 0.0f : v;
}

// Warp 0 only. Lane 0 posts expect_tx for the whole chunk (cnt units x TC
// rows x 128B); then for each owned unit, lanes 0..TC-1 issue one row copy.
static __device__ __forceinline__ void issue_chunk_warp0(LifSmem* sm, int c,
                                                         const float* in,
                                                         int start, int cnt, int lane) {
    const int s = c & (NSTAGE - 1);
    const unsigned mb = smem_u32(&sm->mbar[s]);
    if (lane == 0) mbar_expect_tx(mb, (unsigned)cnt * TC * UNIT_ROW_BYTES);
    if (lane < TC) {
        const int t = c * TC + lane;
        #pragma unroll
        for (int k = 0; k < MAXU; ++k) {
            if (k < cnt) {
                const int u  = start + k;
                const int ub = u >> 5;               // batch of this unit
                const int un = (u & 31) << 5;        // first neuron of unit
                const float* src = in + (long long)ub * (LIF_T * LIF_N)
                                      + (long long)t * LIF_N + un;
                bulk_g2s(smem_u32(&sm->tile[s][lane][k << 5]), src,
                         UNIT_ROW_BYTES, mb);
            }
        }
    }
}

static __global__ __launch_bounds__(NTHREAD)
void lif_scan_kernel(const float* __restrict__ in,
                     const float* __restrict__ v0,
                     float* __restrict__ out)
{
    extern __shared__ char smem_raw[];
    LifSmem* sm = reinterpret_cast<LifSmem*>(smem_raw);

    const int tid  = threadIdx.x;
    const int lane = tid & 31;
    const int bid  = blockIdx.x;

    // Unit assignment: 136 CTAs x 7 units + 12 CTAs x 6 units = 1024 units.
    int start, cnt;
    if (bid < 136) { start = bid * 7;              cnt = 7; }
    else           { start = 952 + (bid - 136) * 6; cnt = 6; }

    const int  myu    = tid >> 5;
    const bool active = (myu < cnt);
    const int  u      = start + (active ? myu : 0);
    const int  b      = u >> 5;
    const int  n      = ((u & 31) << 5) + lane;

    if (tid == 0) {
        #pragma unroll
        for (int i = 0; i < NSTAGE; ++i)
            mbar_init(smem_u32(&sm->mbar[i]), 1);
        asm volatile("fence.proxy.async.shared::cta;" ::: "memory");
    }
    __syncthreads();

    // Prologue: fill all pipeline stages (warp 0, lane-parallel issue).
    if (tid < 32) {
        #pragma unroll
        for (int c = 0; c < NSTAGE; ++c)
            issue_chunk_warp0(sm, c, in, start, cnt, lane);
    }

    // Per-thread state: 1 neuron.
    float v = active ? v0[(long long)b * LIF_N + n] : 0.0f;

    float* sp = out + (long long)b * (LIF_T * LIF_N) + n;          // spikes
    float* vp = sp + (long long)LIF_B * LIF_T * LIF_N;             // voltages

    #pragma unroll 1
    for (int c = 0; c < NCHUNK; ++c) {
        const int s = c & (NSTAGE - 1);
        const unsigned parity = (c >> 3) & 1;

        mbar_wait(smem_u32(&sm->mbar[s]), parity);

        #pragma unroll
        for (int r = 0; r < TC; ++r) {
            float cur = sm->tile[s][r][tid];
            float spk;
            v = lif_step(v, cur, spk);
            if (active) {
                const long long off = (long long)(c * TC + r) * LIF_N;
                __stcs(sp + off, spk);
                __stcs(vp + off, v);
            }
        }

        __syncthreads();   // all threads done reading stage s -> safe to refill

        if (tid < 32 && c + NSTAGE < NCHUNK)
            issue_chunk_warp0(sm, c + NSTAGE, in, start, cnt, lane);
    }
}

extern "C" void kernel_launch(void* const* d_in, const int* in_sizes, int n_in,
                              void* d_out, int out_size)
{
    const float* in = (const float*)d_in[0];   // [B, T, N]
    const float* v0 = (const float*)d_in[1];   // [B, N]
    float* out = (float*)d_out;                // [2, B, T, N]

    (void)in_sizes; (void)n_in; (void)out_size;

    const int smem_bytes = (int)sizeof(LifSmem);   // ~143 KB -> 1 CTA/SM
    cudaFuncSetAttribute(lif_scan_kernel,
                         cudaFuncAttributeMaxDynamicSharedMemorySize, smem_bytes);

    lif_scan_kernel<<<NCTA, NTHREAD, smem_bytes>>>(in, v0, out);
}

// round 8
// speedup vs baseline: 3.0240x; 3.0240x over previous
#include <cuda_runtime.h>
#include <cuda.h>
#include <cstdint>

// LIF neuron scan — balanced 148-CTA persistent tiling with 3D tensor-TMA
// box loads (one per 32-neuron unit per chunk), register compute, streamed
// coalesced scalar stores.
//
// Inputs : d_in[0] = input_current  f32 [B=32, T=1000, N=1024]
//          d_in[1] = v_init         f32 [B=32, N=1024]
// Output : d_out = [2, B, T, N] f32  (spikes block, then voltages block)
//
// Recurrence:
//   v = v + (i - v) / 10.0     (correctly-rounded div via Markstein FMA seq)
//   s = (v >= 1.0) ? 1 : 0
//   v = s ? 0 : v

#define LIF_B   32
#define LIF_T   1000
#define LIF_N   1024
#define TC      20                     // timesteps per chunk
#define NSTAGE  8                      // input pipeline depth
#define MAXU    7                      // max units (32-neuron blocks) per CTA
#define NTHREAD (MAXU * 32)            // 224 threads
#define NCHUNK  (LIF_T / TC)           // 50
#define UNIT_BYTES (TC * 32 * 4)       // 2560 per unit per chunk
#define NCTA    148

struct LifSmem {
    // Per stage: MAXU contiguous [TC][32] unit blocks (TMA box destination).
    float tile[NSTAGE][MAXU][TC][32];  // 8*7*20*32*4 = 143360 B
    unsigned long long mbar[NSTAGE];
};

static __device__ __forceinline__ unsigned smem_u32(const void* p) {
    return (unsigned)__cvta_generic_to_shared(p);
}

static __device__ __forceinline__ void mbar_init(unsigned mbar, unsigned count) {
    asm volatile("mbarrier.init.shared.b64 [%0], %1;" :: "r"(mbar), "r"(count) : "memory");
}

static __device__ __forceinline__ void mbar_expect_tx(unsigned mbar, unsigned bytes) {
    asm volatile("mbarrier.arrive.expect_tx.shared.b64 _, [%0], %1;"
                 :: "r"(mbar), "r"(bytes) : "memory");
}

static __device__ __forceinline__ void mbar_wait(unsigned mbar, unsigned parity) {
    asm volatile(
        "{\n\t"
        ".reg .pred P1;\n\t"
        "LAB_WAIT_%=:\n\t"
        "mbarrier.try_wait.parity.acquire.cta.shared::cta.b64 P1, [%0], %1, 0x989680;\n\t"
        "@P1 bra LAB_DONE_%=;\n\t"
        "bra LAB_WAIT_%=;\n\t"
        "LAB_DONE_%=:\n\t"
        "}"
        :: "r"(mbar), "r"(parity) : "memory");
}

static __device__ __forceinline__ void tma_load_box(unsigned dst_smem,
                                                    const CUtensorMap* map,
                                                    int x, int y, int z,
                                                    unsigned mbar) {
    asm volatile(
        "cp.async.bulk.tensor.3d.shared::cta.global.tile.mbarrier::complete_tx::bytes "
        "[%0], [%1, {%2, %3, %4}], [%5];"
        :: "r"(dst_smem), "l"(map), "r"(x), "r"(y), "r"(z), "r"(mbar) : "memory");
}

static __device__ __forceinline__ float lif_step(float v, float i, float& s_out) {
    float x  = i - v;                  // (-(v - 0) + i)
    float q0 = x * 0.1f;               // Markstein: correctly-rounded x/10
    float e  = fmaf(-10.0f, q0, x);
    float q  = fmaf(e, 0.1f, q0);
    v = v + q;
    s_out = (v >= 1.0f) ? 1.0f : 0.0f;
    return (v >= 1.0f) ? 0.0f : v;
}

// Warp 0 only. Lane 0 posts expect_tx; lanes 0..cnt-1 each issue ONE
// 3D tensor-TMA box load [32 x TC x 1] for their unit.
static __device__ __forceinline__ void issue_chunk_warp0(LifSmem* sm, int c,
                                                         const CUtensorMap* map,
                                                         int start, int cnt, int lane) {
    const int s = c & (NSTAGE - 1);
    const unsigned mb = smem_u32(&sm->mbar[s]);
    if (lane == 0) mbar_expect_tx(mb, (unsigned)cnt * UNIT_BYTES);
    if (lane < cnt) {
        const int u  = start + lane;
        const int ub = u >> 5;               // batch of this unit
        const int un = (u & 31) << 5;        // first neuron of unit
        tma_load_box(smem_u32(&sm->tile[s][lane][0][0]), map,
                     un, c * TC, ub, mb);
    }
}

static __global__ __launch_bounds__(NTHREAD)
void lif_scan_kernel(const __grid_constant__ CUtensorMap tmap,
                     const float* __restrict__ v0,
                     float* __restrict__ out)
{
    extern __shared__ char smem_raw[];
    LifSmem* sm = reinterpret_cast<LifSmem*>(smem_raw);

    const int tid  = threadIdx.x;
    const int lane = tid & 31;
    const int bid  = blockIdx.x;

    // Unit assignment: 136 CTAs x 7 units + 12 CTAs x 6 units = 1024 units.
    int start, cnt;
    if (bid < 136) { start = bid * 7;               cnt = 7; }
    else           { start = 952 + (bid - 136) * 6; cnt = 6; }

    const int  myu    = tid >> 5;
    const bool active = (myu < cnt);
    const int  u      = start + (active ? myu : 0);
    const int  b      = u >> 5;
    const int  n      = ((u & 31) << 5) + lane;

    if (tid == 0) {
        #pragma unroll
        for (int i = 0; i < NSTAGE; ++i)
            mbar_init(smem_u32(&sm->mbar[i]), 1);
        asm volatile("fence.proxy.async.shared::cta;" ::: "memory");
    }
    __syncthreads();

    // Prologue: fill all pipeline stages (warp 0).
    if (tid < 32) {
        #pragma unroll
        for (int c = 0; c < NSTAGE; ++c)
            issue_chunk_warp0(sm, c, &tmap, start, cnt, lane);
    }

    // Per-thread state: 1 neuron.
    float v = active ? v0[(long long)b * LIF_N + n] : 0.0f;

    float* sp = out + (long long)b * (LIF_T * LIF_N) + n;          // spikes
    float* vp = sp + (long long)LIF_B * LIF_T * LIF_N;             // voltages

    #pragma unroll 1
    for (int c = 0; c < NCHUNK; ++c) {
        const int s = c & (NSTAGE - 1);
        const unsigned parity = (c >> 3) & 1;

        mbar_wait(smem_u32(&sm->mbar[s]), parity);

        if (active) {
            #pragma unroll
            for (int r = 0; r < TC; ++r) {
                float cur = sm->tile[s][myu][r][lane];
                float spk;
                v = lif_step(v, cur, spk);
                const long long off = (long long)(c * TC + r) * LIF_N;
                __stcs(sp + off, spk);
                __stcs(vp + off, v);
            }
        }

        __syncthreads();   // all threads done reading stage s -> safe to refill

        if (tid < 32 && c + NSTAGE < NCHUNK)
            issue_chunk_warp0(sm, c + NSTAGE, &tmap, start, cnt, lane);
    }
}

typedef CUresult (*EncodeTiledFn)(
    CUtensorMap*, CUtensorMapDataType, cuuint32_t, void*,
    const cuuint64_t*, const cuuint64_t*, const cuuint32_t*, const cuuint32_t*,
    CUtensorMapInterleave, CUtensorMapSwizzle, CUtensorMapL2promotion,
    CUtensorMapFloatOOBfill);

extern "C" void kernel_launch(void* const* d_in, const int* in_sizes, int n_in,
                              void* d_out, int out_size)
{
    const float* in = (const float*)d_in[0];   // [B, T, N]
    const float* v0 = (const float*)d_in[1];   // [B, N]
    float* out = (float*)d_out;                // [2, B, T, N]

    (void)in_sizes; (void)n_in; (void)out_size;

    // Fetch cuTensorMapEncodeTiled through the runtime (no -lcuda needed).
    void* fn_ptr = nullptr;
    cudaDriverEntryPointQueryResult qres;
    cudaGetDriverEntryPointByVersion("cuTensorMapEncodeTiled", &fn_ptr, 12000,
                                     cudaEnableDefault, &qres);
    EncodeTiledFn encode = (EncodeTiledFn)fn_ptr;

    // 3D map over input_current: dim0=N (contiguous), dim1=T, dim2=B.
    CUtensorMap tmap;
    cuuint64_t dims[3]    = {LIF_N, LIF_T, LIF_B};
    cuuint64_t strides[2] = {(cuuint64_t)LIF_N * 4,
                             (cuuint64_t)LIF_T * LIF_N * 4};
    cuuint32_t box[3]     = {32, TC, 1};
    cuuint32_t estr[3]    = {1, 1, 1};
    encode(&tmap, CU_TENSOR_MAP_DATA_TYPE_FLOAT32, 3, (void*)in,
           dims, strides, box, estr,
           CU_TENSOR_MAP_INTERLEAVE_NONE, CU_TENSOR_MAP_SWIZZLE_NONE,
           CU_TENSOR_MAP_L2_PROMOTION_L2_128B, CU_TENSOR_MAP_FLOAT_OOB_FILL_NONE);

    const int smem_bytes = (int)sizeof(LifSmem);   // ~143 KB -> 1 CTA/SM
    cudaFuncSetAttribute(lif_scan_kernel,
                         cudaFuncAttributeMaxDynamicSharedMemorySize, smem_bytes);

    lif_scan_kernel<<<NCTA, NTHREAD, smem_bytes>>>(tmap, v0, out);
}